// round 16
// baseline (speedup 1.0000x reference)
#include <cuda_runtime.h>
#include <cuda_bf16.h>
#include <cstdint>

// Inputs (metadata order):
//   d_in[0] = x      float32 [262144]  (1 MB, random-gathered, L2-resident)
//   d_in[1] = A_vals float32 [NNZ]
//   d_in[2] = A_rows int32   [NNZ]
//   d_in[3] = A_cols int32   [NNZ]
// Output: float32 [262144]
//
// Unsorted-COO SpMV at the co-saturated L1tex/LTS floor (65.1us kernel, 512thr
// geometry optimum). R16: SpMV accumulates into a statically-zero __device__
// scratch (first graph node, no predecessor); the finalize kernel (publish
// out = scratch, reset scratch = 0) is launched with PROGRAMMATIC DEPENDENT
// LAUNCH so its launch ramp overlaps the SpMV — only the ~3MB copy remains
// exposed after SpMV completion. R15 measured finalize at 4.7us fully serial;
// PDL targets the ~2.5-3us ramp component.

#define THREADS 512
#define OUT_N   262144

__device__ float g_scratch[OUT_N];   // zero-initialized at module load

__global__ void __launch_bounds__(THREADS) coo_spmv_kernel(
    const float*  __restrict__ x,
    const float4* __restrict__ vals4,
    const int4*   __restrict__ rows4,
    const int4*   __restrict__ cols4,
    int nnz4)
{
    int i = blockIdx.x * blockDim.x + threadIdx.x;
    if (i >= nnz4) return;

    // Three independent 16B streaming loads -> MLP 3 per thread.
    float4 v = __ldg(&vals4[i]);
    int4   r = __ldg(&rows4[i]);
    int4   c = __ldg(&cols4[i]);

    // Random gathers from L2-resident x (1 MB).
    float x0 = __ldg(&x[c.x]);
    float x1 = __ldg(&x[c.y]);
    float x2 = __ldg(&x[c.z]);
    float x3 = __ldg(&x[c.w]);

    // Scatter-add into the zero-maintained scratch accumulator.
    atomicAdd(&g_scratch[r.x], v.x * x0);
    atomicAdd(&g_scratch[r.y], v.y * x1);
    atomicAdd(&g_scratch[r.z], v.z * x2);
    atomicAdd(&g_scratch[r.w], v.w * x3);
}

// Scalar tail accumulator (nnz % 4 != 0; unused for this shape).
__global__ void coo_spmv_tail_kernel(
    const float* __restrict__ x,
    const float* __restrict__ vals,
    const int*   __restrict__ rows,
    const int*   __restrict__ cols,
    int start, int nnz)
{
    int i = start + blockIdx.x * blockDim.x + threadIdx.x;
    if (i < nnz) {
        atomicAdd(&g_scratch[rows[i]], vals[i] * __ldg(&x[cols[i]]));
    }
}

// Publish result and restore the scratch-is-zero invariant for the next
// replay. Launched with PDL: grid ramps up during the SpMV; the griddepsync
// releases once the SpMV (and all its atomics) have completed and flushed.
__global__ void __launch_bounds__(THREADS) finalize_kernel(
    float* __restrict__ out, int n)
{
    int i = blockIdx.x * blockDim.x + threadIdx.x;

    // Wait for the preceding grid (SpMV) to complete; memory visible after.
    cudaGridDependencySynchronize();

    if (i < n) {
        out[i] = g_scratch[i];
        g_scratch[i] = 0.f;
    }
}

extern "C" void kernel_launch(void* const* d_in, const int* in_sizes, int n_in,
                              void* d_out, int out_size) {
    const float* x    = (const float*)d_in[0];
    const float* vals = (const float*)d_in[1];
    const int*   rows = (const int*)d_in[2];
    const int*   cols = (const int*)d_in[3];
    float* out = (float*)d_out;

    const int nnz  = in_sizes[1];
    const int nnz4 = nnz / 4;

    // Node 1 (no predecessor): SpMV into zero-maintained scratch.
    if (nnz4 > 0) {
        int blocks = (nnz4 + THREADS - 1) / THREADS;   // 4096 for this shape
        coo_spmv_kernel<<<blocks, THREADS>>>(
            x, (const float4*)vals, (const int4*)rows, (const int4*)cols, nnz4);
    }

    // Tail (nnz % 4): empty for this shape -> no node enters the graph.
    int tail_start = nnz4 * 4;
    int tail = nnz - tail_start;
    if (tail > 0) {
        coo_spmv_tail_kernel<<<(tail + 255) / 256, 256>>>(
            x, vals, rows, cols, tail_start, nnz);
    }

    // Node 2: finalize, launched with programmatic dependent launch so its
    // ramp overlaps the SpMV. 262144 scalar threads for max copy parallelism.
    {
        cudaLaunchConfig_t cfg = {};
        cfg.gridDim  = dim3((OUT_N + THREADS - 1) / THREADS, 1, 1);  // 512
        cfg.blockDim = dim3(THREADS, 1, 1);
        cfg.dynamicSmemBytes = 0;
        cfg.stream = 0;
        cudaLaunchAttribute attr[1];
        attr[0].id = cudaLaunchAttributeProgrammaticStreamSerialization;
        attr[0].val.programmaticStreamSerializationAllowed = 1;
        cfg.attrs = attr;
        cfg.numAttrs = 1;
        cudaLaunchKernelEx(&cfg, finalize_kernel, out, (int)OUT_N);
    }
}

// round 17
// speedup vs baseline: 1.0050x; 1.0050x over previous
#include <cuda_runtime.h>
#include <cuda_bf16.h>
#include <cstdint>

// Inputs (metadata order):
//   d_in[0] = x      float32 [262144]  (1 MB, random-gathered, L2-resident)
//   d_in[1] = A_vals float32 [NNZ]     (streamed once)
//   d_in[2] = A_rows int32   [NNZ]     (streamed once)
//   d_in[3] = A_cols int32   [NNZ]     (streamed once)
// Output: float32 [262144]
//
// FINAL (16 rounds): unsorted-COO SpMV at the co-saturated L1tex/LTS floor.
// Kernel = 65.0-65.3us: 8.39M divergent 32B-sector gathers + 8.39M spread
// RED.E.ADD.F32 lanes + 100MB stream; irreducible for uniform-random indices.
// Geometry optimum measured: 512thr/4096CTA (256->66.9, 512->65.1, 1024->67.2).
// Falsified: L1 cache-policy hints (x3 neutral), DSMEM cluster gather (3x
// worse), TMA-staged streams (neutral), smem x-slice (occupancy collapse),
// fused zero+spin-gate (25% worse), scratch+finalize topology (+0.4us),
// PDL epilogue (neutral). Init-first 2-node graph is the cheapest topology.

#define THREADS 512

__global__ void zero_out_kernel(float4* __restrict__ out, int n4) {
    int i = blockIdx.x * blockDim.x + threadIdx.x;
    if (i < n4) out[i] = make_float4(0.f, 0.f, 0.f, 0.f);
}

__global__ void __launch_bounds__(THREADS) coo_spmv_kernel(
    const float*  __restrict__ x,
    const float4* __restrict__ vals4,
    const int4*   __restrict__ rows4,
    const int4*   __restrict__ cols4,
    float*        __restrict__ out,
    int nnz4)
{
    int i = blockIdx.x * blockDim.x + threadIdx.x;
    if (i >= nnz4) return;

    // Three independent 16B streaming loads -> MLP 3 per thread.
    float4 v = __ldg(&vals4[i]);
    int4   r = __ldg(&rows4[i]);
    int4   c = __ldg(&cols4[i]);

    // Random gathers from L2-resident x (1 MB).
    float x0 = __ldg(&x[c.x]);
    float x1 = __ldg(&x[c.y]);
    float x2 = __ldg(&x[c.z]);
    float x3 = __ldg(&x[c.w]);

    // Scatter-add: return value unused -> RED.E.ADD.F32 at L2.
    atomicAdd(&out[r.x], v.x * x0);
    atomicAdd(&out[r.y], v.y * x1);
    atomicAdd(&out[r.z], v.z * x2);
    atomicAdd(&out[r.w], v.w * x3);
}

// Tail handler for nnz not divisible by 4 (host-guarded out for this shape).
__global__ void coo_spmv_tail_kernel(
    const float* __restrict__ x,
    const float* __restrict__ vals,
    const int*   __restrict__ rows,
    const int*   __restrict__ cols,
    float*       __restrict__ out,
    int start, int nnz)
{
    int i = start + blockIdx.x * blockDim.x + threadIdx.x;
    if (i < nnz) {
        atomicAdd(&out[rows[i]], vals[i] * __ldg(&x[cols[i]]));
    }
}

extern "C" void kernel_launch(void* const* d_in, const int* in_sizes, int n_in,
                              void* d_out, int out_size) {
    const float* x    = (const float*)d_in[0];
    const float* vals = (const float*)d_in[1];
    const int*   rows = (const int*)d_in[2];
    const int*   cols = (const int*)d_in[3];
    float* out = (float*)d_out;

    const int nnz = in_sizes[1];

    // Zero-init output (harness poisons it to 0xAA).
    {
        int n4 = out_size / 4;               // out_size divisible by 4 here
        zero_out_kernel<<<(n4 + 255) / 256, 256>>>((float4*)out, n4);
    }

    // Main vectorized COO pass: 4 nnz per thread, 512-thread blocks (optimum).
    int nnz4 = nnz / 4;
    if (nnz4 > 0) {
        int blocks = (nnz4 + THREADS - 1) / THREADS;   // 4096 for this shape
        coo_spmv_kernel<<<blocks, THREADS>>>(
            x, (const float4*)vals, (const int4*)rows, (const int4*)cols, out, nnz4);
    }

    // Tail (nnz % 4): empty for this shape -> no node enters the graph.
    int tail_start = nnz4 * 4;
    int tail = nnz - tail_start;
    if (tail > 0) {
        coo_spmv_tail_kernel<<<(tail + 255) / 256, 256>>>(
            x, vals, rows, cols, out, tail_start, nnz);
    }
}